// round 13
// baseline (speedup 1.0000x reference)
#include <cuda_runtime.h>
#include <cstdint>

#define NCH 8
#define HW 512
#define IMG (HW*HW)
#define CROP 506
#define CIMG (CROP*CROP)
#define NSHIFT 81

// 12 nonzero taps of the 13-tap half-pixel kernel, offsets -6..+5
__constant__ float c_w12[12] = {
    -1.20162964e-4f,  1.615524292e-3f, -1.0385513306e-2f,  4.3619155884e-2f,
    -1.45397186478e-1f, 6.1066818237e-1f, 6.1066818237e-1f, -1.45397186478e-1f,
     4.3619155884e-2f, -1.0385513306e-2f, 1.615524292e-3f, -1.20162964e-4f };

// device scratch (static: allocation is forbidden)
__device__ float g_tmp [NCH*IMG];
__device__ float g_p   [NCH*IMG];
__device__ float g_p2e [NCH*IMG];
__device__ float g_p2s [NCH*IMG];
__device__ float g_p2se[NCH*IMG];
__device__ float g_ap  [NCH*CIMG];
__device__ float g_sii [NCH*CIMG];
__device__ float g_kx  [NCH*41];
__device__ float g_ky  [NCH*41];
__device__ double g_rho[NSHIFT*NCH];
// parity-field precompute (translation-invariant interior)
__device__ float g_tmp4[4*NCH*IMG];
__device__ float g_bp  [4*NCH*IMG];
__device__ float g_sjj [4*NCH*IMG];

__device__ __forceinline__ const float* parity_img(int pk) {
    return (pk == 0) ? g_p : (pk == 1) ? g_p2e : (pk == 2) ? g_p2s : g_p2se;
}

__global__ void k_zero() {
    int t = blockIdx.x*blockDim.x + threadIdx.x;
    if (t < NSHIFT*NCH) g_rho[t] = 0.0;
}

// exact separable factors of the rank-1 Gaussian MTF kernel
__global__ void k_sepfac(const float* __restrict__ K) {
    int c = blockIdx.x; int t = threadIdx.x;
    __shared__ float cm[41];
    __shared__ float tot;
    const float* Kc = K + c*1681;
    if (t < 41) { float s = 0.f; for (int y = 0; y < 41; ++y) s += Kc[y*41+t]; cm[t] = s; }
    __syncthreads();
    if (t == 0) { float s = 0.f; for (int i = 0; i < 41; ++i) s += cm[i]; tot = s; }
    __syncthreads();
    if (t < 41) {
        g_kx[c*41+t] = cm[t];
        float r = 0.f; for (int x = 0; x < 41; ++x) r += Kc[t*41+x];
        g_ky[c*41+t] = r / tot;
    }
}

// 41-tap horizontal Gaussian with edge clamp, 8 outputs/thread
__global__ void k_gaussH(const float* __restrict__ pan) {
    int i = blockIdx.x*blockDim.x + threadIdx.x;
    if (i >= NCH*512*64) return;
    int c = i >> 15; int rem = i & 32767;
    int y = rem >> 6; int x0 = (rem & 63) << 3;
    const float* row = pan + c*IMG + (y<<9);
    const float* w = g_kx + c*41;
    float v[48];
#pragma unroll
    for (int t = 0; t < 48; ++t) { int xx = x0 + t - 20; xx = min(511, max(0, xx)); v[t] = row[xx]; }
    float s[8];
#pragma unroll
    for (int j = 0; j < 8; ++j) s[j] = 0.f;
#pragma unroll
    for (int t = 0; t < 41; ++t) {
        float wt = w[t];
#pragma unroll
        for (int j = 0; j < 8; ++j) s[j] += wt * v[t+j];
    }
    float* o = g_tmp + c*IMG + (y<<9) + x0;
#pragma unroll
    for (int j = 0; j < 8; ++j) o[j] = s[j];
}

// 41-tap vertical Gaussian with edge clamp
__global__ void k_gaussV() {
    int i = blockIdx.x*blockDim.x + threadIdx.x;
    if (i >= NCH*512*64) return;
    int c = i >> 15; int rem = i & 32767;
    int yg = rem >> 9; int x = rem & 511;
    int y0 = yg << 3;
    const float* col = g_tmp + c*IMG + x;
    const float* w = g_ky + c*41;
    float v[48];
#pragma unroll
    for (int t = 0; t < 48; ++t) { int yy = y0 + t - 20; yy = min(511, max(0, yy)); v[t] = col[yy<<9]; }
    float s[8];
#pragma unroll
    for (int j = 0; j < 8; ++j) s[j] = 0.f;
#pragma unroll
    for (int t = 0; t < 41; ++t) {
        float wt = w[t];
#pragma unroll
        for (int j = 0; j < 8; ++j) s[j] += wt * v[t+j];
    }
    float* o = g_p + c*IMG + (y0<<9) + x;
#pragma unroll
    for (int j = 0; j < 8; ++j) o[j<<9] = s[j];
}

// 12-tap half-pixel filter, SAME zero-pad, horizontal: g_p -> g_p2e
__global__ void k_c13h(int which) {
    const float* in = g_p; float* out = g_p2e; (void)which;
    int i = blockIdx.x*blockDim.x + threadIdx.x;
    if (i >= NCH*512*64) return;
    int c = i >> 15; int rem = i & 32767;
    int y = rem >> 6; int x0 = (rem & 63) << 3;
    const float* row = in + c*IMG + (y<<9);
    float v[19];
#pragma unroll
    for (int t = 0; t < 19; ++t) { int xx = x0 + t - 6; v[t] = ((unsigned)xx < 512u) ? row[xx] : 0.f; }
    float s[8];
#pragma unroll
    for (int j = 0; j < 8; ++j) s[j] = 0.f;
#pragma unroll
    for (int t = 0; t < 12; ++t) {
        float wt = c_w12[t];
#pragma unroll
        for (int j = 0; j < 8; ++j) s[j] += wt * v[t+j];
    }
    float* o = out + c*IMG + (y<<9) + x0;
#pragma unroll
    for (int j = 0; j < 8; ++j) o[j] = s[j];
}

// vertical variant. which: 0 = g_p->g_p2s, 1 = g_p2e->g_p2se
__global__ void k_c13v(int which) {
    const float* in = which ? g_p2e : g_p;
    float* out = which ? g_p2se : g_p2s;
    int i = blockIdx.x*blockDim.x + threadIdx.x;
    if (i >= NCH*512*64) return;
    int c = i >> 15; int rem = i & 32767;
    int yg = rem >> 9; int x = rem & 511;
    int y0 = yg << 3;
    const float* col = in + c*IMG + x;
    float v[19];
#pragma unroll
    for (int t = 0; t < 19; ++t) { int yy = y0 + t - 6; v[t] = ((unsigned)yy < 512u) ? col[yy<<9] : 0.f; }
    float s[8];
#pragma unroll
    for (int j = 0; j < 8; ++j) s[j] = 0.f;
#pragma unroll
    for (int t = 0; t < 12; ++t) {
        float wt = c_w12[t];
#pragma unroll
        for (int j = 0; j < 8; ++j) s[j] += wt * v[t+j];
    }
    float* o = out + c*IMG + (y0<<9) + x;
#pragma unroll
    for (int j = 0; j < 8; ++j) o[j<<9] = s[j];
}

// ---- ms-side precompute with sliding windows (box window offsets -7..+8, zero pad) ----
__global__ void k_ahsum(const float* __restrict__ ms) {
    int seg = threadIdx.x;
    int y = blockIdx.x, c = blockIdx.y;
    int x0 = seg << 3;
    if (x0 >= CROP) return;
    const float* row = ms + c*IMG + (y+3)*512 + 3;
    float* o = g_tmp + c*IMG + y*CROP;
    float s = 0.f;
    for (int dx = -7; dx <= 8; ++dx) { int xx = x0 + dx; if ((unsigned)xx < (unsigned)CROP) s += row[xx]; }
    o[x0] = s;
    int x1 = min(x0 + 8, CROP);
    for (int x = x0 + 1; x < x1; ++x) {
        int xa = x + 8, xr = x - 8;
        if (xa < CROP) s += row[xa];
        if (xr >= 0)   s -= row[xr];
        o[x] = s;
    }
}
__global__ void k_aprime(const float* __restrict__ ms) {
    int x = blockIdx.x*blockDim.x + threadIdx.x;
    if (x >= CROP) return;
    int yseg = blockIdx.y, c = blockIdx.z;
    int y0 = yseg << 3;
    if (y0 >= CROP) return;
    const float* col = g_tmp + c*IMG;
    float s = 0.f;
    for (int dy = -7; dy <= 8; ++dy) { int yy = y0 + dy; if ((unsigned)yy < (unsigned)CROP) s += col[yy*CROP + x]; }
    int y1 = min(y0 + 8, CROP);
    for (int y = y0; y < y1; ++y) {
        if (y > y0) {
            int ya = y + 8, yr = y - 8;
            if (ya < CROP) s += col[ya*CROP + x];
            if (yr >= 0)   s -= col[yr*CROP + x];
        }
        float a = ms[c*IMG + (y+3)*512 + (x+3)];
        g_ap[c*CIMG + y*CROP + x] = a - s * (1.0f/256.0f);
    }
}
__global__ void k_sqh() {
    int seg = threadIdx.x;
    int y = blockIdx.x, c = blockIdx.y;
    int x0 = seg << 3;
    if (x0 >= CROP) return;
    const float* row = g_ap + c*CIMG + y*CROP;
    float* o = g_tmp + c*IMG + y*CROP;
    float s = 0.f;
    for (int dx = -7; dx <= 8; ++dx) { int xx = x0 + dx; if ((unsigned)xx < (unsigned)CROP) { float v = row[xx]; s += v*v; } }
    o[x0] = s;
    int x1 = min(x0 + 8, CROP);
    for (int x = x0 + 1; x < x1; ++x) {
        int xa = x + 8, xr = x - 8;
        if (xa < CROP) { float v = row[xa]; s += v*v; }
        if (xr >= 0)   { float v = row[xr]; s -= v*v; }
        o[x] = s;
    }
}
__global__ void k_sii() {
    int x = blockIdx.x*blockDim.x + threadIdx.x;
    if (x >= CROP) return;
    int yseg = blockIdx.y, c = blockIdx.z;
    int y0 = yseg << 3;
    if (y0 >= CROP) return;
    const float* col = g_tmp + c*IMG;
    float s = 0.f;
    for (int dy = -7; dy <= 8; ++dy) { int yy = y0 + dy; if ((unsigned)yy < (unsigned)CROP) s += col[yy*CROP + x]; }
    int y1 = min(y0 + 8, CROP);
    for (int y = y0; y < y1; ++y) {
        if (y > y0) {
            int ya = y + 8, yr = y - 8;
            if (ya < CROP) s += col[ya*CROP + x];
            if (yr >= 0)   s -= col[yr*CROP + x];
        }
        g_sii[c*CIMG + y*CROP + x] = fmaxf(s, 1e-20f);
    }
}

// ---- parity-field precompute: bp = img - box16(img)/256 ; sjj = box16(bp^2) ----
__global__ void k_bph() {
    int seg = threadIdx.x;
    int y = blockIdx.x, c = blockIdx.y, pk = blockIdx.z;
    int x0 = seg << 3;
    const float* row = parity_img(pk) + c*IMG + (y<<9);
    float* o = g_tmp4 + (pk*NCH + c)*IMG + (y<<9);
    float s = 0.f;
    for (int dx = -7; dx <= 8; ++dx) { int xx = x0 + dx; if ((unsigned)xx < 512u) s += row[xx]; }
    o[x0] = s;
#pragma unroll
    for (int x = x0 + 1; x < x0 + 8; ++x) {
        int xa = x + 8, xr = x - 8;
        if (xa < 512) s += row[xa];
        if (xr >= 0)  s -= row[xr];
        o[x] = s;
    }
}
__global__ void k_bpv() {
    int x = blockIdx.x*blockDim.x + threadIdx.x;
    int yseg = blockIdx.y;
    int zc = blockIdx.z; int pk = zc >> 3, c = zc & 7;
    int y0 = yseg << 3;
    const float* t4 = g_tmp4 + (pk*NCH + c)*IMG;
    const float* img = parity_img(pk) + c*IMG;
    float* bp = g_bp + (pk*NCH + c)*IMG;
    float s = 0.f;
    for (int dy = -7; dy <= 8; ++dy) { int yy = y0 + dy; if ((unsigned)yy < 512u) s += t4[(yy<<9) + x]; }
#pragma unroll
    for (int y = y0; y < y0 + 8; ++y) {
        if (y > y0) {
            int ya = y + 8, yr = y - 8;
            if (ya < 512) s += t4[(ya<<9) + x];
            if (yr >= 0)  s -= t4[(yr<<9) + x];
        }
        bp[(y<<9) + x] = img[(y<<9) + x] - s * (1.0f/256.0f);
    }
}
__global__ void k_sjh() {
    int seg = threadIdx.x;
    int y = blockIdx.x, c = blockIdx.y, pk = blockIdx.z;
    int x0 = seg << 3;
    const float* row = g_bp + (pk*NCH + c)*IMG + (y<<9);
    float* o = g_tmp4 + (pk*NCH + c)*IMG + (y<<9);
    float s = 0.f;
    for (int dx = -7; dx <= 8; ++dx) { int xx = x0 + dx; if ((unsigned)xx < 512u) { float v = row[xx]; s += v*v; } }
    o[x0] = s;
#pragma unroll
    for (int x = x0 + 1; x < x0 + 8; ++x) {
        int xa = x + 8, xr = x - 8;
        if (xa < 512) { float v = row[xa]; s += v*v; }
        if (xr >= 0)  { float v = row[xr]; s -= v*v; }
        o[x] = s;
    }
}
__global__ void k_sjv() {
    int x = blockIdx.x*blockDim.x + threadIdx.x;
    int yseg = blockIdx.y;
    int zc = blockIdx.z; int pk = zc >> 3, c = zc & 7;
    int y0 = yseg << 3;
    const float* t4 = g_tmp4 + (pk*NCH + c)*IMG;
    float* sj = g_sjj + (pk*NCH + c)*IMG;
    float s = 0.f;
    for (int dy = -7; dy <= 8; ++dy) { int yy = y0 + dy; if ((unsigned)yy < 512u) s += t4[(yy<<9) + x]; }
#pragma unroll
    for (int y = y0; y < y0 + 8; ++y) {
        if (y > y0) {
            int ya = y + 8, yr = y - 8;
            if (ya < 512) s += t4[(ya<<9) + x];
            if (yr >= 0)  s -= t4[(yr<<9) + x];
        }
        sj[(y<<9) + x] = s;
    }
}

// ---------------- boundary rho kernel: b' from g_bp + exact edge strips ----------------
// smem 18388 floats = 73.6 KB -> 3 CTAs/SM
//   SP [0,6320):       sp 79x80 b' tile
//   SC1 [6320,9986):   strip b staging (H: 37x95 / V: 94x39)  -> sa 48x81 overlays later
//   SC2 [9986,12148):  strip partial sums (H vbs 22x94 / V hb 94x23)
//   H23 [12148,18388): h23 48x65 float2
#define BSP_OFF 0
#define BSP_STR 80
#define BSC1_OFF 6320
#define BSC2_OFF 9986
#define BSA_OFF 6320
#define BSA_STR 81
#define BH_OFF 12148
#define BH_STR 65
#define BSMEM_FLOATS 18388

__global__ void __launch_bounds__(512, 3)
k_rho_bnd()
{
    extern __shared__ float sm[];
    float* sp  = sm + BSP_OFF;
    float* sc1 = sm + BSC1_OFF;
    float* sc2 = sm + BSC2_OFF;
    float* sa  = sm + BSA_OFF;
    float2* h23 = (float2*)(sm + BH_OFF);
    float* red = sm;                    // sp dead after final phase E

    const int z = blockIdx.z;
    const int s = z >> 3, c = z & 7;
    const int mi = s / 9, ni = s - mi*9;
    const int ri = (mi >> 1) - 2, ci = (ni >> 1) - 2;
    const int pk = ((mi & 1) << 1) | (ni & 1);
    const float* p2c = parity_img(pk) + c*IMG;
    const float* bpc = g_bp + (pk*NCH + c)*IMG;
    // perimeter tile map
    int bidx = blockIdx.x, tx, ty;
    if (bidx < 8)       { tx = bidx;      ty = 0; }
    else if (bidx < 16) { tx = bidx - 8;  ty = 7; }
    else if (bidx < 22) { tx = 0;         ty = bidx - 15; }
    else                { tx = 7;         ty = bidx - 21; }
    const int y0 = ty << 6, x0 = tx << 6;
    const int tid = threadIdx.x;
    const int offy = 3 - ri, offx = 3 - ci;
    const float* apc = g_ap + c*CIMG;
    const bool hasH = (ty == 0) || (ty == 7);
    const bool hasV = (tx == 0) || (tx == 7);
    const int vaH = (ty == 0) ? 0 : 57, nH = (ty == 0) ? 14 : 22;
    const int uaV = (tx == 0) ? 0 : 57, nV = (tx == 0) ? 14 : 22;

    // phase A': b' from g_bp (exact for all safe pixels; unsafe overwritten by strips)
    for (int k = tid; k < 79*79; k += 512) {
        int i = k / 79, j = k - i*79;
        int y = y0 - 7 + i, x = x0 - 7 + j;
        float v = 0.f;
        if ((unsigned)y < (unsigned)CROP && (unsigned)x < (unsigned)CROP)
            v = bpc[(y + offy)*512 + (x + offx)];
        sp[i*BSP_STR + j] = v;
    }

    // ---- horizontal unsafe strip: b' rows v in [vaH, vaH+nH) ----
    if (hasH) {
        int rowsH = nH + 15;
        for (int k = tid; k < rowsH*94; k += 512) {
            int i = k / 94, j = k - i*94;
            int gy = y0 - 14 + vaH + i, gx = x0 - 14 + j;
            float v = 0.f;
            if ((unsigned)gy < (unsigned)CROP && (unsigned)gx < (unsigned)CROP)
                v = p2c[(gy + offy)*512 + (gx + offx)];
            sc1[i*95 + j] = v;
        }
        __syncthreads();
        // vertical 16-sums: 94 cols x 2 chunks
        if (tid < 188) {
            int u = tid % 94, ck = tid / 94;
            int hn = (nH + 1) >> 1;
            int v0 = ck * hn, v1 = min(v0 + hn, nH);
            if (v0 < v1) {
                float ss = 0.f;
#pragma unroll
                for (int t = 0; t < 16; ++t) ss += sc1[(v0 + t)*95 + u];
                sc2[v0*94 + u] = ss;
                for (int v = v0 + 1; v < v1; ++v) {
                    ss += sc1[(v+15)*95 + u] - sc1[(v-1)*95 + u];
                    sc2[v*94 + u] = ss;
                }
            }
        }
        __syncthreads();
        // horizontal slide -> b' strip rows into sp
        if (tid < nH*6) {
            int vl = tid / 6, ch = tid - (tid/6)*6;
            int u0 = (ch == 0) ? 0 : 14 + 13*(ch - 1);
            int u1 = (ch == 0) ? 14 : u0 + 13;
            const float* vr = sc2 + vl*94;
            float bx = 0.f;
#pragma unroll
            for (int j = 0; j < 16; ++j) bx += vr[u0 + j];
            int v = vaH + vl;
            int gy = y0 - 7 + v;
            bool yok = (unsigned)gy < (unsigned)CROP;
            for (int u = u0; u < u1; ++u) {
                if (u > u0) bx += vr[u+15] - vr[u-1];
                int gx = x0 - 7 + u;
                float bp = 0.f;
                if (yok && (unsigned)gx < (unsigned)CROP)
                    bp = sc1[(vl + 7)*95 + (u + 7)] - bx * (1.0f/256.0f);
                sp[v*BSP_STR + u] = bp;
            }
        }
        __syncthreads();
    }

    // ---- vertical unsafe strip: b' cols u in [uaV, uaV+nV) ----
    if (hasV) {
        int colsV = nV + 15;
        for (int k = tid; k < 94*colsV; k += 512) {
            int i = k / colsV, j = k - i*colsV;
            int gy = y0 - 14 + i, gx = x0 - 14 + uaV + j;
            float v = 0.f;
            if ((unsigned)gy < (unsigned)CROP && (unsigned)gx < (unsigned)CROP)
                v = p2c[(gy + offy)*512 + (gx + offx)];
            sc1[i*39 + j] = v;
        }
        __syncthreads();
        // horizontal 16-sums per row: 94 rows x 2 chunks of cols
        if (tid < 188) {
            int i = tid % 94, ck = tid / 94;
            int hn = (nV + 1) >> 1;
            int u0 = ck * hn, u1 = min(u0 + hn, nV);
            if (u0 < u1) {
                const float* rr = sc1 + i*39;
                float ss = 0.f;
#pragma unroll
                for (int t = 0; t < 16; ++t) ss += rr[u0 + t];
                sc2[i*23 + u0] = ss;
                for (int u = u0 + 1; u < u1; ++u) {
                    ss += rr[u+15] - rr[u-1];
                    sc2[i*23 + u] = ss;
                }
            }
        }
        __syncthreads();
        // vertical slide -> b' strip cols into sp
        if (tid < nV*5) {
            int uc = tid % nV, ck = tid / nV;
            int v0 = ck << 4, v1 = min(v0 + 16, 79);
            float bx = 0.f;
#pragma unroll
            for (int t = 0; t < 16; ++t) bx += sc2[(v0 + t)*23 + uc];
            int u = uaV + uc;
            int gx = x0 - 7 + u;
            bool xok = (unsigned)gx < (unsigned)CROP;
            for (int v = v0; v < v1; ++v) {
                if (v > v0) bx += sc2[(v+15)*23 + uc] - sc2[(v-1)*23 + uc];
                int gy = y0 - 7 + v;
                float bp = 0.f;
                if (xok && (unsigned)gy < (unsigned)CROP)
                    bp = sc1[(v + 7)*39 + (uc + 7)] - bx * (1.0f/256.0f);
                sp[v*BSP_STR + u] = bp;
            }
        }
        __syncthreads();
    }

    // ---- halves: hsum/vsum cascade (exact b' tile now in sp) ----
    float acc = 0.f;
    const float* siic = g_sii + c*CIMG;
#pragma unroll
    for (int half = 0; half < 2; ++half) {
        const int vbase = half << 5;
        // load a' rows [y0-7+vbase, +48) into sa (overlays dead sc1/sc2)
        for (int k = tid; k < 48*79; k += 512) {
            int r = k / 79, j = k - r*79;
            int gy = y0 - 7 + vbase + r, gx = x0 - 7 + j;
            sa[r*BSA_STR + j] = ((unsigned)gy < (unsigned)CROP && (unsigned)gx < (unsigned)CROP)
                                ? apc[gy*CROP + gx] : 0.f;
        }
        __syncthreads();
        // phase D: hsum16 of (b'^2, a'b') -> h23[48][64]
        if (tid < 384) {
            int vr_ = tid >> 3, ch = tid & 7;
            int v = vbase + vr_;
            if (v <= 78) {
                int q0 = ch << 3;
                const float* bpr = sp + v*BSP_STR;
                const float* ar  = sa + vr_*BSA_STR;
                float s2 = 0.f, s3 = 0.f;
#pragma unroll
                for (int t = 0; t < 16; ++t) { float b_ = bpr[q0+t]; s2 += b_*b_; s3 += ar[q0+t]*b_; }
                float2* hr = h23 + vr_*BH_STR;
                hr[q0] = make_float2(s2, s3);
#pragma unroll
                for (int st = 1; st < 8; ++st) {
                    int q = q0 + st;
                    float nb = bpr[q+15], ob = bpr[q-1];
                    s2 += nb*nb - ob*ob;
                    s3 += ar[q+15]*nb - ar[q-1]*ob;
                    hr[q] = make_float2(s2, s3);
                }
            }
        }
        __syncthreads();
        // phase E: vertical 16-sums -> rho for rows p = vbase + seg*4 .. +3
        {
            int q = tid & 63, seg = tid >> 6;
            int pr0 = seg << 2;
            float s2 = 0.f, s3 = 0.f;
#pragma unroll
            for (int t = 0; t < 16; ++t) { float2 w = h23[(pr0+t)*BH_STR + q]; s2 += w.x; s3 += w.y; }
#pragma unroll
            for (int pr = pr0; pr < pr0 + 4; ++pr) {
                if (pr > pr0) {
                    float2 nw = h23[(pr+15)*BH_STR + q], ow = h23[(pr-1)*BH_STR + q];
                    s2 += nw.x - ow.x;
                    s3 += nw.y - ow.y;
                }
                int gy = y0 + vbase + pr, gx = x0 + q;
                if (gy < CROP && gx < CROP) {
                    float sjj = fmaxf(s2, 1e-20f);
                    float den = sqrtf(siic[gy*CROP + gx] * sjj) + 1e-20f;
                    acc += __fdividef(s3, den);
                }
            }
        }
        __syncthreads();
    }

#pragma unroll
    for (int o = 16; o > 0; o >>= 1) acc += __shfl_down_sync(0xffffffffu, acc, o);
    if ((tid & 31) == 0) red[tid >> 5] = acc;
    __syncthreads();
    if (tid < 16) {
        float v = red[tid];
#pragma unroll
        for (int o = 8; o > 0; o >>= 1) v += __shfl_down_sync(0xffffu, v, o, 16);
        if (tid == 0) atomicAdd(&g_rho[z], (double)v);
    }
}

// ---------------- interior rho kernel: 36 tiles, translation-invariant fast path ----------------
#define IPA_STR 81
#define IH3_OFF 12798
#define IH3_STR 65
#define INT_SMEM_FLOATS 17933

__global__ void __launch_bounds__(512, 3)
k_rho_int()
{
    extern __shared__ float sm[];
    float2* pa = (float2*)sm;
    float* h3 = sm + IH3_OFF;
    float* red = sm;

    const int z = blockIdx.z;
    const int s = z >> 3, c = z & 7;
    const int mi = s / 9, ni = s - mi*9;
    const int ri = (mi >> 1) - 2, ci = (ni >> 1) - 2;
    const int pk = ((mi & 1) << 1) | (ni & 1);
    const int y0 = ((int)blockIdx.y + 1) << 6, x0 = ((int)blockIdx.x + 1) << 6;
    const int tid = threadIdx.x;
    const int offy = 3 - ri, offx = 3 - ci;
    const float* bpc = g_bp  + (pk*NCH + c)*IMG;
    const float* sjc = g_sjj + (pk*NCH + c)*IMG;
    const float* apc = g_ap + c*CIMG;
    const float* siic = g_sii + c*CIMG;

    for (int k = tid; k < 79*79; k += 512) {
        int i = k / 79, j = k - i*79;
        int gy = y0 - 7 + i, gx = x0 - 7 + j;
        pa[i*IPA_STR + j] = make_float2(bpc[(gy + offy)*512 + (gx + offx)],
                                        apc[gy*CROP + gx]);
    }
    __syncthreads();

    for (int un = tid; un < 79*8; un += 512) {
        int v = un >> 3, ch = un & 7;
        int q0 = ch << 3;
        const float2* par = pa + v*IPA_STR;
        float s3 = 0.f;
#pragma unroll
        for (int t = 0; t < 16; ++t) { float2 w = par[q0+t]; s3 += w.x*w.y; }
        float* hr = h3 + v*IH3_STR;
        hr[q0] = s3;
#pragma unroll
        for (int st = 1; st < 8; ++st) {
            int q = q0 + st;
            float2 nw = par[q+15], ow = par[q-1];
            s3 += nw.x*nw.y - ow.x*ow.y;
            hr[q] = s3;
        }
    }
    __syncthreads();

    float acc = 0.f;
    {
        int q = tid & 63, seg = tid >> 6;
        int p0 = seg << 3;
        float s3 = 0.f;
#pragma unroll
        for (int t = 0; t < 16; ++t) s3 += h3[(p0+t)*IH3_STR + q];
#pragma unroll
        for (int p = p0; p < p0 + 8; ++p) {
            if (p > p0) s3 += h3[(p+15)*IH3_STR + q] - h3[(p-1)*IH3_STR + q];
            int gy = y0 + p, gx = x0 + q;
            float sjj = fmaxf(sjc[(gy + offy)*512 + (gx + offx)], 1e-20f);
            float den = sqrtf(siic[gy*CROP + gx] * sjj) + 1e-20f;
            acc += __fdividef(s3, den);
        }
    }

#pragma unroll
    for (int o = 16; o > 0; o >>= 1) acc += __shfl_down_sync(0xffffffffu, acc, o);
    if ((tid & 31) == 0) red[tid >> 5] = acc;
    __syncthreads();
    if (tid < 16) {
        float v = red[tid];
#pragma unroll
        for (int o = 8; o > 0; o >>= 1) v += __shfl_down_sync(0xffffu, v, o, 16);
        if (tid == 0) atomicAdd(&g_rho[z], (double)v);
    }
}

__global__ void k_argmax(int* __restrict__ out) {
    int c = threadIdx.x;
    if (c >= NCH) return;
    double best = -1e300; int bi = 0;
    for (int s = 0; s < NSHIFT; ++s) {
        double v = g_rho[s*NCH + c];
        if (v > best) { best = v; bi = s; }
    }
    out[c]       = bi / 9 - 4;
    out[NCH + c] = bi % 9 - 4;
}

extern "C" void kernel_launch(void* const* d_in, const int* in_sizes, int n_in,
                              void* d_out, int out_size) {
    const float* ms  = (const float*)d_in[0];
    const float* pan = (const float*)d_in[1];
    const float* mtf = (const float*)d_in[2];
    int* out = (int*)d_out;
    (void)in_sizes; (void)n_in; (void)out_size;

    cudaFuncSetAttribute(k_rho_bnd, cudaFuncAttributeMaxDynamicSharedMemorySize,
                         BSMEM_FLOATS * (int)sizeof(float));
    cudaFuncSetAttribute(k_rho_int, cudaFuncAttributeMaxDynamicSharedMemorySize,
                         INT_SMEM_FLOATS * (int)sizeof(float));

    k_zero<<<1, 656>>>();
    k_sepfac<<<NCH, 64>>>(mtf);
    k_gaussH<<<1024, 256>>>(pan);
    k_gaussV<<<1024, 256>>>();
    k_c13h<<<1024, 256>>>(0);
    k_c13v<<<1024, 256>>>(0);
    k_c13v<<<1024, 256>>>(1);

    k_ahsum <<<dim3(CROP, NCH), 64>>>(ms);
    k_aprime<<<dim3(4, 64, NCH), 128>>>(ms);
    k_sqh   <<<dim3(CROP, NCH), 64>>>();
    k_sii   <<<dim3(4, 64, NCH), 128>>>();

    k_bph<<<dim3(512, NCH, 4), 64>>>();
    k_bpv<<<dim3(4, 64, 4*NCH), 128>>>();
    k_sjh<<<dim3(512, NCH, 4), 64>>>();
    k_sjv<<<dim3(4, 64, 4*NCH), 128>>>();

    k_rho_bnd<<<dim3(28, 1, NSHIFT*NCH), 512, BSMEM_FLOATS * (int)sizeof(float)>>>();
    k_rho_int<<<dim3(6, 6, NSHIFT*NCH), 512, INT_SMEM_FLOATS * (int)sizeof(float)>>>();
    k_argmax<<<1, 32>>>(out);
}

// round 14
// speedup vs baseline: 1.1472x; 1.1472x over previous
#include <cuda_runtime.h>
#include <cstdint>

#define NCH 8
#define HW 512
#define IMG (HW*HW)
#define CROP 506
#define CIMG (CROP*CROP)
#define NSHIFT 81

// 12 nonzero taps of the 13-tap half-pixel kernel, offsets -6..+5
__constant__ float c_w12[12] = {
    -1.20162964e-4f,  1.615524292e-3f, -1.0385513306e-2f,  4.3619155884e-2f,
    -1.45397186478e-1f, 6.1066818237e-1f, 6.1066818237e-1f, -1.45397186478e-1f,
     4.3619155884e-2f, -1.0385513306e-2f, 1.615524292e-3f, -1.20162964e-4f };

// device scratch (static: allocation is forbidden)
__device__ float g_tmp [NCH*IMG];
__device__ float g_p   [NCH*IMG];
__device__ float g_p2e [NCH*IMG];
__device__ float g_p2s [NCH*IMG];
__device__ float g_p2se[NCH*IMG];
__device__ float g_ap  [NCH*CIMG];
__device__ float g_sii [NCH*CIMG];     // holds rsii = rsqrt(max(sii,1e-20))
__device__ float g_kx  [NCH*41];
__device__ float g_ky  [NCH*41];
__device__ double g_rho[NSHIFT*NCH];
// parity-field precompute (translation-invariant interior)
__device__ float g_tmp4[4*NCH*IMG];
__device__ float g_bp  [4*NCH*IMG];
__device__ float g_sjj [4*NCH*IMG];    // holds rsjj = rsqrt(max(sjj,1e-20))

__device__ __forceinline__ const float* parity_img(int pk) {
    return (pk == 0) ? g_p : (pk == 1) ? g_p2e : (pk == 2) ? g_p2s : g_p2se;
}

__global__ void k_zero() {
    int t = blockIdx.x*blockDim.x + threadIdx.x;
    if (t < NSHIFT*NCH) g_rho[t] = 0.0;
}

// exact separable factors of the rank-1 Gaussian MTF kernel
__global__ void k_sepfac(const float* __restrict__ K) {
    int c = blockIdx.x; int t = threadIdx.x;
    __shared__ float cm[41];
    __shared__ float tot;
    const float* Kc = K + c*1681;
    if (t < 41) { float s = 0.f; for (int y = 0; y < 41; ++y) s += Kc[y*41+t]; cm[t] = s; }
    __syncthreads();
    if (t == 0) { float s = 0.f; for (int i = 0; i < 41; ++i) s += cm[i]; tot = s; }
    __syncthreads();
    if (t < 41) {
        g_kx[c*41+t] = cm[t];
        float r = 0.f; for (int x = 0; x < 41; ++x) r += Kc[t*41+x];
        g_ky[c*41+t] = r / tot;
    }
}

// 41-tap horizontal Gaussian with edge clamp, 8 outputs/thread
__global__ void k_gaussH(const float* __restrict__ pan) {
    int i = blockIdx.x*blockDim.x + threadIdx.x;
    if (i >= NCH*512*64) return;
    int c = i >> 15; int rem = i & 32767;
    int y = rem >> 6; int x0 = (rem & 63) << 3;
    const float* row = pan + c*IMG + (y<<9);
    const float* w = g_kx + c*41;
    float v[48];
#pragma unroll
    for (int t = 0; t < 48; ++t) { int xx = x0 + t - 20; xx = min(511, max(0, xx)); v[t] = row[xx]; }
    float s[8];
#pragma unroll
    for (int j = 0; j < 8; ++j) s[j] = 0.f;
#pragma unroll
    for (int t = 0; t < 41; ++t) {
        float wt = w[t];
#pragma unroll
        for (int j = 0; j < 8; ++j) s[j] += wt * v[t+j];
    }
    float* o = g_tmp + c*IMG + (y<<9) + x0;
#pragma unroll
    for (int j = 0; j < 8; ++j) o[j] = s[j];
}

// 41-tap vertical Gaussian with edge clamp
__global__ void k_gaussV() {
    int i = blockIdx.x*blockDim.x + threadIdx.x;
    if (i >= NCH*512*64) return;
    int c = i >> 15; int rem = i & 32767;
    int yg = rem >> 9; int x = rem & 511;
    int y0 = yg << 3;
    const float* col = g_tmp + c*IMG + x;
    const float* w = g_ky + c*41;
    float v[48];
#pragma unroll
    for (int t = 0; t < 48; ++t) { int yy = y0 + t - 20; yy = min(511, max(0, yy)); v[t] = col[yy<<9]; }
    float s[8];
#pragma unroll
    for (int j = 0; j < 8; ++j) s[j] = 0.f;
#pragma unroll
    for (int t = 0; t < 41; ++t) {
        float wt = w[t];
#pragma unroll
        for (int j = 0; j < 8; ++j) s[j] += wt * v[t+j];
    }
    float* o = g_p + c*IMG + (y0<<9) + x;
#pragma unroll
    for (int j = 0; j < 8; ++j) o[j<<9] = s[j];
}

// 12-tap half-pixel filter, SAME zero-pad, horizontal: g_p -> g_p2e
__global__ void k_c13h(int which) {
    const float* in = g_p; float* out = g_p2e; (void)which;
    int i = blockIdx.x*blockDim.x + threadIdx.x;
    if (i >= NCH*512*64) return;
    int c = i >> 15; int rem = i & 32767;
    int y = rem >> 6; int x0 = (rem & 63) << 3;
    const float* row = in + c*IMG + (y<<9);
    float v[19];
#pragma unroll
    for (int t = 0; t < 19; ++t) { int xx = x0 + t - 6; v[t] = ((unsigned)xx < 512u) ? row[xx] : 0.f; }
    float s[8];
#pragma unroll
    for (int j = 0; j < 8; ++j) s[j] = 0.f;
#pragma unroll
    for (int t = 0; t < 12; ++t) {
        float wt = c_w12[t];
#pragma unroll
        for (int j = 0; j < 8; ++j) s[j] += wt * v[t+j];
    }
    float* o = out + c*IMG + (y<<9) + x0;
#pragma unroll
    for (int j = 0; j < 8; ++j) o[j] = s[j];
}

// vertical variant. which: 0 = g_p->g_p2s, 1 = g_p2e->g_p2se
__global__ void k_c13v(int which) {
    const float* in = which ? g_p2e : g_p;
    float* out = which ? g_p2se : g_p2s;
    int i = blockIdx.x*blockDim.x + threadIdx.x;
    if (i >= NCH*512*64) return;
    int c = i >> 15; int rem = i & 32767;
    int yg = rem >> 9; int x = rem & 511;
    int y0 = yg << 3;
    const float* col = in + c*IMG + x;
    float v[19];
#pragma unroll
    for (int t = 0; t < 19; ++t) { int yy = y0 + t - 6; v[t] = ((unsigned)yy < 512u) ? col[yy<<9] : 0.f; }
    float s[8];
#pragma unroll
    for (int j = 0; j < 8; ++j) s[j] = 0.f;
#pragma unroll
    for (int t = 0; t < 12; ++t) {
        float wt = c_w12[t];
#pragma unroll
        for (int j = 0; j < 8; ++j) s[j] += wt * v[t+j];
    }
    float* o = out + c*IMG + (y0<<9) + x;
#pragma unroll
    for (int j = 0; j < 8; ++j) o[j<<9] = s[j];
}

// ---- ms-side precompute with sliding windows (box window offsets -7..+8, zero pad) ----
__global__ void k_ahsum(const float* __restrict__ ms) {
    int seg = threadIdx.x;
    int y = blockIdx.x, c = blockIdx.y;
    int x0 = seg << 3;
    if (x0 >= CROP) return;
    const float* row = ms + c*IMG + (y+3)*512 + 3;
    float* o = g_tmp + c*IMG + y*CROP;
    float s = 0.f;
    for (int dx = -7; dx <= 8; ++dx) { int xx = x0 + dx; if ((unsigned)xx < (unsigned)CROP) s += row[xx]; }
    o[x0] = s;
    int x1 = min(x0 + 8, CROP);
    for (int x = x0 + 1; x < x1; ++x) {
        int xa = x + 8, xr = x - 8;
        if (xa < CROP) s += row[xa];
        if (xr >= 0)   s -= row[xr];
        o[x] = s;
    }
}
__global__ void k_aprime(const float* __restrict__ ms) {
    int x = blockIdx.x*blockDim.x + threadIdx.x;
    if (x >= CROP) return;
    int yseg = blockIdx.y, c = blockIdx.z;
    int y0 = yseg << 3;
    if (y0 >= CROP) return;
    const float* col = g_tmp + c*IMG;
    float s = 0.f;
    for (int dy = -7; dy <= 8; ++dy) { int yy = y0 + dy; if ((unsigned)yy < (unsigned)CROP) s += col[yy*CROP + x]; }
    int y1 = min(y0 + 8, CROP);
    for (int y = y0; y < y1; ++y) {
        if (y > y0) {
            int ya = y + 8, yr = y - 8;
            if (ya < CROP) s += col[ya*CROP + x];
            if (yr >= 0)   s -= col[yr*CROP + x];
        }
        float a = ms[c*IMG + (y+3)*512 + (x+3)];
        g_ap[c*CIMG + y*CROP + x] = a - s * (1.0f/256.0f);
    }
}
__global__ void k_sqh() {
    int seg = threadIdx.x;
    int y = blockIdx.x, c = blockIdx.y;
    int x0 = seg << 3;
    if (x0 >= CROP) return;
    const float* row = g_ap + c*CIMG + y*CROP;
    float* o = g_tmp + c*IMG + y*CROP;
    float s = 0.f;
    for (int dx = -7; dx <= 8; ++dx) { int xx = x0 + dx; if ((unsigned)xx < (unsigned)CROP) { float v = row[xx]; s += v*v; } }
    o[x0] = s;
    int x1 = min(x0 + 8, CROP);
    for (int x = x0 + 1; x < x1; ++x) {
        int xa = x + 8, xr = x - 8;
        if (xa < CROP) { float v = row[xa]; s += v*v; }
        if (xr >= 0)   { float v = row[xr]; s -= v*v; }
        o[x] = s;
    }
}
// stores rsii = rsqrt(max(sii,1e-20))
__global__ void k_sii() {
    int x = blockIdx.x*blockDim.x + threadIdx.x;
    if (x >= CROP) return;
    int yseg = blockIdx.y, c = blockIdx.z;
    int y0 = yseg << 3;
    if (y0 >= CROP) return;
    const float* col = g_tmp + c*IMG;
    float s = 0.f;
    for (int dy = -7; dy <= 8; ++dy) { int yy = y0 + dy; if ((unsigned)yy < (unsigned)CROP) s += col[yy*CROP + x]; }
    int y1 = min(y0 + 8, CROP);
    for (int y = y0; y < y1; ++y) {
        if (y > y0) {
            int ya = y + 8, yr = y - 8;
            if (ya < CROP) s += col[ya*CROP + x];
            if (yr >= 0)   s -= col[yr*CROP + x];
        }
        g_sii[c*CIMG + y*CROP + x] = rsqrtf(fmaxf(s, 1e-20f));
    }
}

// ---- parity-field precompute: bp = img - box16(img)/256 ; rsjj = rsqrt(box16(bp^2)) ----
__global__ void k_bph() {
    int seg = threadIdx.x;
    int y = blockIdx.x, c = blockIdx.y, pk = blockIdx.z;
    int x0 = seg << 3;
    const float* row = parity_img(pk) + c*IMG + (y<<9);
    float* o = g_tmp4 + (pk*NCH + c)*IMG + (y<<9);
    float s = 0.f;
    for (int dx = -7; dx <= 8; ++dx) { int xx = x0 + dx; if ((unsigned)xx < 512u) s += row[xx]; }
    o[x0] = s;
#pragma unroll
    for (int x = x0 + 1; x < x0 + 8; ++x) {
        int xa = x + 8, xr = x - 8;
        if (xa < 512) s += row[xa];
        if (xr >= 0)  s -= row[xr];
        o[x] = s;
    }
}
__global__ void k_bpv() {
    int x = blockIdx.x*blockDim.x + threadIdx.x;
    int yseg = blockIdx.y;
    int zc = blockIdx.z; int pk = zc >> 3, c = zc & 7;
    int y0 = yseg << 3;
    const float* t4 = g_tmp4 + (pk*NCH + c)*IMG;
    const float* img = parity_img(pk) + c*IMG;
    float* bp = g_bp + (pk*NCH + c)*IMG;
    float s = 0.f;
    for (int dy = -7; dy <= 8; ++dy) { int yy = y0 + dy; if ((unsigned)yy < 512u) s += t4[(yy<<9) + x]; }
#pragma unroll
    for (int y = y0; y < y0 + 8; ++y) {
        if (y > y0) {
            int ya = y + 8, yr = y - 8;
            if (ya < 512) s += t4[(ya<<9) + x];
            if (yr >= 0)  s -= t4[(yr<<9) + x];
        }
        bp[(y<<9) + x] = img[(y<<9) + x] - s * (1.0f/256.0f);
    }
}
__global__ void k_sjh() {
    int seg = threadIdx.x;
    int y = blockIdx.x, c = blockIdx.y, pk = blockIdx.z;
    int x0 = seg << 3;
    const float* row = g_bp + (pk*NCH + c)*IMG + (y<<9);
    float* o = g_tmp4 + (pk*NCH + c)*IMG + (y<<9);
    float s = 0.f;
    for (int dx = -7; dx <= 8; ++dx) { int xx = x0 + dx; if ((unsigned)xx < 512u) { float v = row[xx]; s += v*v; } }
    o[x0] = s;
#pragma unroll
    for (int x = x0 + 1; x < x0 + 8; ++x) {
        int xa = x + 8, xr = x - 8;
        if (xa < 512) { float v = row[xa]; s += v*v; }
        if (xr >= 0)  { float v = row[xr]; s -= v*v; }
        o[x] = s;
    }
}
// stores rsjj = rsqrt(max(sjj,1e-20))
__global__ void k_sjv() {
    int x = blockIdx.x*blockDim.x + threadIdx.x;
    int yseg = blockIdx.y;
    int zc = blockIdx.z; int pk = zc >> 3, c = zc & 7;
    int y0 = yseg << 3;
    const float* t4 = g_tmp4 + (pk*NCH + c)*IMG;
    float* sj = g_sjj + (pk*NCH + c)*IMG;
    float s = 0.f;
    for (int dy = -7; dy <= 8; ++dy) { int yy = y0 + dy; if ((unsigned)yy < 512u) s += t4[(yy<<9) + x]; }
#pragma unroll
    for (int y = y0; y < y0 + 8; ++y) {
        if (y > y0) {
            int ya = y + 8, yr = y - 8;
            if (ya < 512) s += t4[(ya<<9) + x];
            if (yr >= 0)  s -= t4[(yr<<9) + x];
        }
        sj[(y<<9) + x] = rsqrtf(fmaxf(s, 1e-20f));
    }
}

// ---------------- boundary rho kernel (exact, R9/R10 pipeline): 28 perimeter tiles ----------------
#define SB_OFF 0
#define VB_OFF 8930
#define SP_OFF 16435
#define SMEM_FLOATS 22834
#define SB_STR 95
#define VB_STR 95
#define SP_STR 81
#define H_STR 66

__global__ void __launch_bounds__(512, 2)
k_rho_bnd()
{
    extern __shared__ float sm[];
    float* sb = sm + SB_OFF;
    float* vb = sm + VB_OFF;
    float* sp = sm + SP_OFF;
    float2* h23 = (float2*)sm;
    float* red = sm + SP_OFF;

    const int z = blockIdx.z;
    const int s = z >> 3, c = z & 7;
    const int mi = s / 9, ni = s - mi*9;
    const int ri = (mi >> 1) - 2, ci = (ni >> 1) - 2;
    const int pk = ((mi & 1) << 1) | (ni & 1);
    const float* p2k = parity_img(pk);
    // perimeter tile map
    int bidx = blockIdx.x, tx, ty;
    if (bidx < 8)       { tx = bidx;      ty = 0; }
    else if (bidx < 16) { tx = bidx - 8;  ty = 7; }
    else if (bidx < 22) { tx = 0;         ty = bidx - 15; }
    else                { tx = 7;         ty = bidx - 21; }
    const int y0 = ty << 6, x0 = tx << 6;
    const int tid = threadIdx.x;
    const int offy = 3 - ri, offx = 3 - ci;
    const float* p2c = p2k + c*IMG;
    const float* apc = g_ap + c*CIMG;

    for (int k = tid; k < 94*94; k += 512) {
        int i = k / 94, j = k - i*94;
        int gy = y0 - 14 + i, gx = x0 - 14 + j;
        float v = 0.f;
        if ((unsigned)gy < (unsigned)CROP && (unsigned)gx < (unsigned)CROP)
            v = p2c[(gy + offy)*512 + (gx + offx)];
        sb[i*SB_STR + j] = v;
    }
    __syncthreads();

    if (tid < 470) {
        int u = tid % 94, c4 = tid / 94;
        int v0 = c4 << 4, v1 = min(v0 + 16, 79);
        float ss = 0.f;
#pragma unroll
        for (int t = 0; t < 16; ++t) ss += sb[(v0 + t)*SB_STR + u];
        vb[v0*VB_STR + u] = ss;
        for (int v = v0 + 1; v < v1; ++v) {
            ss += sb[(v+15)*SB_STR + u] - sb[(v-1)*SB_STR + u];
            vb[v*VB_STR + u] = ss;
        }
    }
    __syncthreads();

    if (tid < 474) {
        int v = tid % 79, ch = tid / 79;
        int u0 = (ch == 0) ? 0 : 14 + 13*(ch - 1);
        int u1 = (ch == 0) ? 14 : u0 + 13;
        const float* vr = vb + v*VB_STR;
        float bx = 0.f;
#pragma unroll
        for (int j = 0; j < 16; ++j) bx += vr[u0 + j];
        int gy = y0 - 7 + v;
        bool yok = (unsigned)gy < (unsigned)CROP;
        for (int u = u0; u < u1; ++u) {
            if (u > u0) bx += vr[u+15] - vr[u-1];
            float bp = 0.f;
            int gx = x0 - 7 + u;
            if (yok && (unsigned)gx < (unsigned)CROP)
                bp = sb[(v+7)*SB_STR + (u+7)] - bx * (1.0f/256.0f);
            sp[v*SP_STR + u] = bp;
        }
    }
    __syncthreads();

    for (int un = tid; un < 79*8; un += 512) {
        int v = un >> 3, ch = un & 7;
        int q0 = ch << 3;
        int gy = y0 - 7 + v;
        float av[24];
        if ((unsigned)gy < (unsigned)CROP) {
            const float* ar = apc + gy*CROP;
#pragma unroll
            for (int k = 0; k < 24; ++k) {
                int gx = x0 - 8 + q0 + k;
                av[k] = ((unsigned)gx < (unsigned)CROP) ? ar[gx] : 0.f;
            }
        } else {
#pragma unroll
            for (int k = 0; k < 24; ++k) av[k] = 0.f;
        }
        const float* bpr = sp + v*SP_STR;
        float s2 = 0.f, s3 = 0.f;
#pragma unroll
        for (int t = 0; t < 16; ++t) { float b_ = bpr[q0+t]; s2 += b_*b_; s3 += av[t+1]*b_; }
        float2* hr = h23 + v*H_STR;
        hr[q0] = make_float2(s2, s3);
#pragma unroll
        for (int st = 1; st < 8; ++st) {
            int q = q0 + st;
            float nb = bpr[q+15], ob = bpr[q-1];
            s2 += nb*nb - ob*ob;
            s3 += av[st+16]*nb - av[st]*ob;
            hr[q] = make_float2(s2, s3);
        }
    }
    __syncthreads();

    float acc = 0.f;
    const float* rsiic = g_sii + c*CIMG;
    {
        int q = tid & 63, seg = tid >> 6;
        int p0 = seg << 3;
        float s2 = 0.f, s3 = 0.f;
#pragma unroll
        for (int t = 0; t < 16; ++t) { float2 w = h23[(p0+t)*H_STR + q]; s2 += w.x; s3 += w.y; }
#pragma unroll
        for (int p = p0; p < p0 + 8; ++p) {
            if (p > p0) {
                float2 nw = h23[(p+15)*H_STR + q], ow = h23[(p-1)*H_STR + q];
                s2 += nw.x - ow.x;
                s3 += nw.y - ow.y;
            }
            int gy = y0 + p, gx = x0 + q;
            if (gy < CROP && gx < CROP) {
                float rj = rsqrtf(fmaxf(s2, 1e-20f));
                acc += s3 * rsiic[gy*CROP + gx] * rj;
            }
        }
    }

#pragma unroll
    for (int o = 16; o > 0; o >>= 1) acc += __shfl_down_sync(0xffffffffu, acc, o);
    if ((tid & 31) == 0) red[tid >> 5] = acc;
    __syncthreads();
    if (tid < 16) {
        float v = red[tid];
#pragma unroll
        for (int o = 8; o > 0; o >>= 1) v += __shfl_down_sync(0xffffu, v, o, 16);
        if (tid == 0) atomicAdd(&g_rho[z], (double)v);
    }
}

// ---------------- interior rho kernel: 36 tiles, translation-invariant fast path ----------------
#define IPA_STR 81
#define IH3_OFF 12798
#define IH3_STR 65
#define INT_SMEM_FLOATS 17933

__global__ void __launch_bounds__(512, 3)
k_rho_int()
{
    extern __shared__ float sm[];
    float2* pa = (float2*)sm;
    float* h3 = sm + IH3_OFF;
    float* red = sm;

    const int z = blockIdx.z;
    const int s = z >> 3, c = z & 7;
    const int mi = s / 9, ni = s - mi*9;
    const int ri = (mi >> 1) - 2, ci = (ni >> 1) - 2;
    const int pk = ((mi & 1) << 1) | (ni & 1);
    const int y0 = ((int)blockIdx.y + 1) << 6, x0 = ((int)blockIdx.x + 1) << 6;
    const int tid = threadIdx.x;
    const int offy = 3 - ri, offx = 3 - ci;
    const float* bpc = g_bp  + (pk*NCH + c)*IMG;
    const float* rsjc = g_sjj + (pk*NCH + c)*IMG;
    const float* apc = g_ap + c*CIMG;
    const float* rsiic = g_sii + c*CIMG;

    for (int k = tid; k < 79*79; k += 512) {
        int i = k / 79, j = k - i*79;
        int gy = y0 - 7 + i, gx = x0 - 7 + j;
        pa[i*IPA_STR + j] = make_float2(bpc[(gy + offy)*512 + (gx + offx)],
                                        apc[gy*CROP + gx]);
    }
    __syncthreads();

    for (int un = tid; un < 79*8; un += 512) {
        int v = un >> 3, ch = un & 7;
        int q0 = ch << 3;
        const float2* par = pa + v*IPA_STR;
        float s3 = 0.f;
#pragma unroll
        for (int t = 0; t < 16; ++t) { float2 w = par[q0+t]; s3 += w.x*w.y; }
        float* hr = h3 + v*IH3_STR;
        hr[q0] = s3;
#pragma unroll
        for (int st = 1; st < 8; ++st) {
            int q = q0 + st;
            float2 nw = par[q+15], ow = par[q-1];
            s3 += nw.x*nw.y - ow.x*ow.y;
            hr[q] = s3;
        }
    }
    __syncthreads();

    float acc = 0.f;
    {
        int q = tid & 63, seg = tid >> 6;
        int p0 = seg << 3;
        float s3 = 0.f;
#pragma unroll
        for (int t = 0; t < 16; ++t) s3 += h3[(p0+t)*IH3_STR + q];
#pragma unroll
        for (int p = p0; p < p0 + 8; ++p) {
            if (p > p0) s3 += h3[(p+15)*IH3_STR + q] - h3[(p-1)*IH3_STR + q];
            int gy = y0 + p, gx = x0 + q;
            acc += s3 * rsiic[gy*CROP + gx] * rsjc[(gy + offy)*512 + (gx + offx)];
        }
    }

#pragma unroll
    for (int o = 16; o > 0; o >>= 1) acc += __shfl_down_sync(0xffffffffu, acc, o);
    if ((tid & 31) == 0) red[tid >> 5] = acc;
    __syncthreads();
    if (tid < 16) {
        float v = red[tid];
#pragma unroll
        for (int o = 8; o > 0; o >>= 1) v += __shfl_down_sync(0xffffu, v, o, 16);
        if (tid == 0) atomicAdd(&g_rho[z], (double)v);
    }
}

__global__ void k_argmax(int* __restrict__ out) {
    int c = threadIdx.x;
    if (c >= NCH) return;
    double best = -1e300; int bi = 0;
    for (int s = 0; s < NSHIFT; ++s) {
        double v = g_rho[s*NCH + c];
        if (v > best) { best = v; bi = s; }
    }
    out[c]       = bi / 9 - 4;
    out[NCH + c] = bi % 9 - 4;
}

extern "C" void kernel_launch(void* const* d_in, const int* in_sizes, int n_in,
                              void* d_out, int out_size) {
    const float* ms  = (const float*)d_in[0];
    const float* pan = (const float*)d_in[1];
    const float* mtf = (const float*)d_in[2];
    int* out = (int*)d_out;
    (void)in_sizes; (void)n_in; (void)out_size;

    cudaFuncSetAttribute(k_rho_bnd, cudaFuncAttributeMaxDynamicSharedMemorySize,
                         SMEM_FLOATS * (int)sizeof(float));
    cudaFuncSetAttribute(k_rho_int, cudaFuncAttributeMaxDynamicSharedMemorySize,
                         INT_SMEM_FLOATS * (int)sizeof(float));

    k_zero<<<1, 656>>>();
    k_sepfac<<<NCH, 64>>>(mtf);
    k_gaussH<<<1024, 256>>>(pan);
    k_gaussV<<<1024, 256>>>();
    k_c13h<<<1024, 256>>>(0);
    k_c13v<<<1024, 256>>>(0);
    k_c13v<<<1024, 256>>>(1);

    k_ahsum <<<dim3(CROP, NCH), 64>>>(ms);
    k_aprime<<<dim3(4, 64, NCH), 128>>>(ms);
    k_sqh   <<<dim3(CROP, NCH), 64>>>();
    k_sii   <<<dim3(4, 64, NCH), 128>>>();

    k_bph<<<dim3(512, NCH, 4), 64>>>();
    k_bpv<<<dim3(4, 64, 4*NCH), 128>>>();
    k_sjh<<<dim3(512, NCH, 4), 64>>>();
    k_sjv<<<dim3(4, 64, 4*NCH), 128>>>();

    k_rho_bnd<<<dim3(28, 1, NSHIFT*NCH), 512, SMEM_FLOATS * (int)sizeof(float)>>>();
    k_rho_int<<<dim3(6, 6, NSHIFT*NCH), 512, INT_SMEM_FLOATS * (int)sizeof(float)>>>();
    k_argmax<<<1, 32>>>(out);
}

// round 16
// speedup vs baseline: 1.4317x; 1.2480x over previous
#include <cuda_runtime.h>
#include <cstdint>

#define NCH 8
#define HW 512
#define IMG (HW*HW)
#define CROP 506
#define CIMG (CROP*CROP)
#define NSHIFT 81

// 12 nonzero taps of the 13-tap half-pixel kernel, offsets -6..+5
__constant__ float c_w12[12] = {
    -1.20162964e-4f,  1.615524292e-3f, -1.0385513306e-2f,  4.3619155884e-2f,
    -1.45397186478e-1f, 6.1066818237e-1f, 6.1066818237e-1f, -1.45397186478e-1f,
     4.3619155884e-2f, -1.0385513306e-2f, 1.615524292e-3f, -1.20162964e-4f };

// device scratch (static: allocation is forbidden)
__device__ float g_tmp [NCH*IMG];
__device__ float g_p   [NCH*IMG];
__device__ float g_p2e [NCH*IMG];
__device__ float g_p2s [NCH*IMG];
__device__ float g_p2se[NCH*IMG];
__device__ float g_ap  [NCH*CIMG];
__device__ float g_sii [NCH*CIMG];     // holds rsii = rsqrt(max(sii,1e-20))
__device__ float g_kx  [NCH*41];
__device__ float g_ky  [NCH*41];
__device__ double g_rho[NSHIFT*NCH];
// parity-field precompute (translation-invariant interior)
__device__ float g_tmp4[4*NCH*IMG];
__device__ float g_bp  [4*NCH*IMG];
__device__ float g_sjj [4*NCH*IMG];    // holds rsjj = rsqrt(max(sjj,1e-20))

__device__ __forceinline__ const float* parity_img(int pk) {
    return (pk == 0) ? g_p : (pk == 1) ? g_p2e : (pk == 2) ? g_p2s : g_p2se;
}

__global__ void k_zero() {
    int t = blockIdx.x*blockDim.x + threadIdx.x;
    if (t < NSHIFT*NCH) g_rho[t] = 0.0;
}

// exact separable factors of the rank-1 Gaussian MTF kernel
__global__ void k_sepfac(const float* __restrict__ K) {
    int c = blockIdx.x; int t = threadIdx.x;
    __shared__ float cm[41];
    __shared__ float tot;
    const float* Kc = K + c*1681;
    if (t < 41) { float s = 0.f; for (int y = 0; y < 41; ++y) s += Kc[y*41+t]; cm[t] = s; }
    __syncthreads();
    if (t == 0) { float s = 0.f; for (int i = 0; i < 41; ++i) s += cm[i]; tot = s; }
    __syncthreads();
    if (t < 41) {
        g_kx[c*41+t] = cm[t];
        float r = 0.f; for (int x = 0; x < 41; ++x) r += Kc[t*41+x];
        g_ky[c*41+t] = r / tot;
    }
}

// 41-tap horizontal Gaussian with edge clamp, 8 outputs/thread
__global__ void k_gaussH(const float* __restrict__ pan) {
    int i = blockIdx.x*blockDim.x + threadIdx.x;
    if (i >= NCH*512*64) return;
    int c = i >> 15; int rem = i & 32767;
    int y = rem >> 6; int x0 = (rem & 63) << 3;
    const float* row = pan + c*IMG + (y<<9);
    const float* w = g_kx + c*41;
    float v[48];
#pragma unroll
    for (int t = 0; t < 48; ++t) { int xx = x0 + t - 20; xx = min(511, max(0, xx)); v[t] = row[xx]; }
    float s[8];
#pragma unroll
    for (int j = 0; j < 8; ++j) s[j] = 0.f;
#pragma unroll
    for (int t = 0; t < 41; ++t) {
        float wt = w[t];
#pragma unroll
        for (int j = 0; j < 8; ++j) s[j] += wt * v[t+j];
    }
    float* o = g_tmp + c*IMG + (y<<9) + x0;
#pragma unroll
    for (int j = 0; j < 8; ++j) o[j] = s[j];
}

// 41-tap vertical Gaussian with edge clamp
__global__ void k_gaussV() {
    int i = blockIdx.x*blockDim.x + threadIdx.x;
    if (i >= NCH*512*64) return;
    int c = i >> 15; int rem = i & 32767;
    int yg = rem >> 9; int x = rem & 511;
    int y0 = yg << 3;
    const float* col = g_tmp + c*IMG + x;
    const float* w = g_ky + c*41;
    float v[48];
#pragma unroll
    for (int t = 0; t < 48; ++t) { int yy = y0 + t - 20; yy = min(511, max(0, yy)); v[t] = col[yy<<9]; }
    float s[8];
#pragma unroll
    for (int j = 0; j < 8; ++j) s[j] = 0.f;
#pragma unroll
    for (int t = 0; t < 41; ++t) {
        float wt = w[t];
#pragma unroll
        for (int j = 0; j < 8; ++j) s[j] += wt * v[t+j];
    }
    float* o = g_p + c*IMG + (y0<<9) + x;
#pragma unroll
    for (int j = 0; j < 8; ++j) o[j<<9] = s[j];
}

// 12-tap half-pixel filter, SAME zero-pad, horizontal: g_p -> g_p2e
__global__ void k_c13h(int which) {
    const float* in = g_p; float* out = g_p2e; (void)which;
    int i = blockIdx.x*blockDim.x + threadIdx.x;
    if (i >= NCH*512*64) return;
    int c = i >> 15; int rem = i & 32767;
    int y = rem >> 6; int x0 = (rem & 63) << 3;
    const float* row = in + c*IMG + (y<<9);
    float v[19];
#pragma unroll
    for (int t = 0; t < 19; ++t) { int xx = x0 + t - 6; v[t] = ((unsigned)xx < 512u) ? row[xx] : 0.f; }
    float s[8];
#pragma unroll
    for (int j = 0; j < 8; ++j) s[j] = 0.f;
#pragma unroll
    for (int t = 0; t < 12; ++t) {
        float wt = c_w12[t];
#pragma unroll
        for (int j = 0; j < 8; ++j) s[j] += wt * v[t+j];
    }
    float* o = out + c*IMG + (y<<9) + x0;
#pragma unroll
    for (int j = 0; j < 8; ++j) o[j] = s[j];
}

// vertical variant. which: 0 = g_p->g_p2s, 1 = g_p2e->g_p2se
__global__ void k_c13v(int which) {
    const float* in = which ? g_p2e : g_p;
    float* out = which ? g_p2se : g_p2s;
    int i = blockIdx.x*blockDim.x + threadIdx.x;
    if (i >= NCH*512*64) return;
    int c = i >> 15; int rem = i & 32767;
    int yg = rem >> 9; int x = rem & 511;
    int y0 = yg << 3;
    const float* col = in + c*IMG + x;
    float v[19];
#pragma unroll
    for (int t = 0; t < 19; ++t) { int yy = y0 + t - 6; v[t] = ((unsigned)yy < 512u) ? col[yy<<9] : 0.f; }
    float s[8];
#pragma unroll
    for (int j = 0; j < 8; ++j) s[j] = 0.f;
#pragma unroll
    for (int t = 0; t < 12; ++t) {
        float wt = c_w12[t];
#pragma unroll
        for (int j = 0; j < 8; ++j) s[j] += wt * v[t+j];
    }
    float* o = out + c*IMG + (y0<<9) + x;
#pragma unroll
    for (int j = 0; j < 8; ++j) o[j<<9] = s[j];
}

// ---- ms-side precompute with sliding windows (box window offsets -7..+8, zero pad) ----
__global__ void k_ahsum(const float* __restrict__ ms) {
    int seg = threadIdx.x;
    int y = blockIdx.x, c = blockIdx.y;
    int x0 = seg << 3;
    if (x0 >= CROP) return;
    const float* row = ms + c*IMG + (y+3)*512 + 3;
    float* o = g_tmp + c*IMG + y*CROP;
    float s = 0.f;
    for (int dx = -7; dx <= 8; ++dx) { int xx = x0 + dx; if ((unsigned)xx < (unsigned)CROP) s += row[xx]; }
    o[x0] = s;
    int x1 = min(x0 + 8, CROP);
    for (int x = x0 + 1; x < x1; ++x) {
        int xa = x + 8, xr = x - 8;
        if (xa < CROP) s += row[xa];
        if (xr >= 0)   s -= row[xr];
        o[x] = s;
    }
}
__global__ void k_aprime(const float* __restrict__ ms) {
    int x = blockIdx.x*blockDim.x + threadIdx.x;
    if (x >= CROP) return;
    int yseg = blockIdx.y, c = blockIdx.z;
    int y0 = yseg << 3;
    if (y0 >= CROP) return;
    const float* col = g_tmp + c*IMG;
    float s = 0.f;
    for (int dy = -7; dy <= 8; ++dy) { int yy = y0 + dy; if ((unsigned)yy < (unsigned)CROP) s += col[yy*CROP + x]; }
    int y1 = min(y0 + 8, CROP);
    for (int y = y0; y < y1; ++y) {
        if (y > y0) {
            int ya = y + 8, yr = y - 8;
            if (ya < CROP) s += col[ya*CROP + x];
            if (yr >= 0)   s -= col[yr*CROP + x];
        }
        float a = ms[c*IMG + (y+3)*512 + (x+3)];
        g_ap[c*CIMG + y*CROP + x] = a - s * (1.0f/256.0f);
    }
}
__global__ void k_sqh() {
    int seg = threadIdx.x;
    int y = blockIdx.x, c = blockIdx.y;
    int x0 = seg << 3;
    if (x0 >= CROP) return;
    const float* row = g_ap + c*CIMG + y*CROP;
    float* o = g_tmp + c*IMG + y*CROP;
    float s = 0.f;
    for (int dx = -7; dx <= 8; ++dx) { int xx = x0 + dx; if ((unsigned)xx < (unsigned)CROP) { float v = row[xx]; s += v*v; } }
    o[x0] = s;
    int x1 = min(x0 + 8, CROP);
    for (int x = x0 + 1; x < x1; ++x) {
        int xa = x + 8, xr = x - 8;
        if (xa < CROP) { float v = row[xa]; s += v*v; }
        if (xr >= 0)   { float v = row[xr]; s -= v*v; }
        o[x] = s;
    }
}
// stores rsii = rsqrt(max(sii,1e-20))
__global__ void k_sii() {
    int x = blockIdx.x*blockDim.x + threadIdx.x;
    if (x >= CROP) return;
    int yseg = blockIdx.y, c = blockIdx.z;
    int y0 = yseg << 3;
    if (y0 >= CROP) return;
    const float* col = g_tmp + c*IMG;
    float s = 0.f;
    for (int dy = -7; dy <= 8; ++dy) { int yy = y0 + dy; if ((unsigned)yy < (unsigned)CROP) s += col[yy*CROP + x]; }
    int y1 = min(y0 + 8, CROP);
    for (int y = y0; y < y1; ++y) {
        if (y > y0) {
            int ya = y + 8, yr = y - 8;
            if (ya < CROP) s += col[ya*CROP + x];
            if (yr >= 0)   s -= col[yr*CROP + x];
        }
        g_sii[c*CIMG + y*CROP + x] = rsqrtf(fmaxf(s, 1e-20f));
    }
}

// ---- parity-field precompute: bp = img - box16(img)/256 ; rsjj = rsqrt(box16(bp^2)) ----
__global__ void k_bph() {
    int seg = threadIdx.x;
    int y = blockIdx.x, c = blockIdx.y, pk = blockIdx.z;
    int x0 = seg << 3;
    const float* row = parity_img(pk) + c*IMG + (y<<9);
    float* o = g_tmp4 + (pk*NCH + c)*IMG + (y<<9);
    float s = 0.f;
    for (int dx = -7; dx <= 8; ++dx) { int xx = x0 + dx; if ((unsigned)xx < 512u) s += row[xx]; }
    o[x0] = s;
#pragma unroll
    for (int x = x0 + 1; x < x0 + 8; ++x) {
        int xa = x + 8, xr = x - 8;
        if (xa < 512) s += row[xa];
        if (xr >= 0)  s -= row[xr];
        o[x] = s;
    }
}
__global__ void k_bpv() {
    int x = blockIdx.x*blockDim.x + threadIdx.x;
    int yseg = blockIdx.y;
    int zc = blockIdx.z; int pk = zc >> 3, c = zc & 7;
    int y0 = yseg << 3;
    const float* t4 = g_tmp4 + (pk*NCH + c)*IMG;
    const float* img = parity_img(pk) + c*IMG;
    float* bp = g_bp + (pk*NCH + c)*IMG;
    float s = 0.f;
    for (int dy = -7; dy <= 8; ++dy) { int yy = y0 + dy; if ((unsigned)yy < 512u) s += t4[(yy<<9) + x]; }
#pragma unroll
    for (int y = y0; y < y0 + 8; ++y) {
        if (y > y0) {
            int ya = y + 8, yr = y - 8;
            if (ya < 512) s += t4[(ya<<9) + x];
            if (yr >= 0)  s -= t4[(yr<<9) + x];
        }
        bp[(y<<9) + x] = img[(y<<9) + x] - s * (1.0f/256.0f);
    }
}
__global__ void k_sjh() {
    int seg = threadIdx.x;
    int y = blockIdx.x, c = blockIdx.y, pk = blockIdx.z;
    int x0 = seg << 3;
    const float* row = g_bp + (pk*NCH + c)*IMG + (y<<9);
    float* o = g_tmp4 + (pk*NCH + c)*IMG + (y<<9);
    float s = 0.f;
    for (int dx = -7; dx <= 8; ++dx) { int xx = x0 + dx; if ((unsigned)xx < 512u) { float v = row[xx]; s += v*v; } }
    o[x0] = s;
#pragma unroll
    for (int x = x0 + 1; x < x0 + 8; ++x) {
        int xa = x + 8, xr = x - 8;
        if (xa < 512) { float v = row[xa]; s += v*v; }
        if (xr >= 0)  { float v = row[xr]; s -= v*v; }
        o[x] = s;
    }
}
// stores rsjj = rsqrt(max(sjj,1e-20))
__global__ void k_sjv() {
    int x = blockIdx.x*blockDim.x + threadIdx.x;
    int yseg = blockIdx.y;
    int zc = blockIdx.z; int pk = zc >> 3, c = zc & 7;
    int y0 = yseg << 3;
    const float* t4 = g_tmp4 + (pk*NCH + c)*IMG;
    float* sj = g_sjj + (pk*NCH + c)*IMG;
    float s = 0.f;
    for (int dy = -7; dy <= 8; ++dy) { int yy = y0 + dy; if ((unsigned)yy < 512u) s += t4[(yy<<9) + x]; }
#pragma unroll
    for (int y = y0; y < y0 + 8; ++y) {
        if (y > y0) {
            int ya = y + 8, yr = y - 8;
            if (ya < 512) s += t4[(ya<<9) + x];
            if (yr >= 0)  s -= t4[(yr<<9) + x];
        }
        sj[(y<<9) + x] = rsqrtf(fmaxf(s, 1e-20f));
    }
}

// ---------------- boundary rho kernel (exact, R14 pipeline): 28 perimeter tiles ----------------
#define SB_OFF 0
#define VB_OFF 8930
#define SP_OFF 16435
#define SMEM_FLOATS 22834
#define SB_STR 95
#define VB_STR 95
#define SP_STR 81
#define H_STR 66

__global__ void __launch_bounds__(512, 2)
k_rho_bnd()
{
    extern __shared__ float sm[];
    float* sb = sm + SB_OFF;
    float* vb = sm + VB_OFF;
    float* sp = sm + SP_OFF;
    float2* h23 = (float2*)sm;
    float* red = sm + SP_OFF;

    const int z = blockIdx.z;
    const int s = z >> 3, c = z & 7;
    const int mi = s / 9, ni = s - mi*9;
    const int ri = (mi >> 1) - 2, ci = (ni >> 1) - 2;
    const int pk = ((mi & 1) << 1) | (ni & 1);
    const float* p2k = parity_img(pk);
    // perimeter tile map
    int bidx = blockIdx.x, tx, ty;
    if (bidx < 8)       { tx = bidx;      ty = 0; }
    else if (bidx < 16) { tx = bidx - 8;  ty = 7; }
    else if (bidx < 22) { tx = 0;         ty = bidx - 15; }
    else                { tx = 7;         ty = bidx - 21; }
    const int y0 = ty << 6, x0 = tx << 6;
    const int tid = threadIdx.x;
    const int offy = 3 - ri, offx = 3 - ci;
    const float* p2c = p2k + c*IMG;
    const float* apc = g_ap + c*CIMG;

    for (int k = tid; k < 94*94; k += 512) {
        int i = k / 94, j = k - i*94;
        int gy = y0 - 14 + i, gx = x0 - 14 + j;
        float v = 0.f;
        if ((unsigned)gy < (unsigned)CROP && (unsigned)gx < (unsigned)CROP)
            v = p2c[(gy + offy)*512 + (gx + offx)];
        sb[i*SB_STR + j] = v;
    }
    __syncthreads();

    if (tid < 470) {
        int u = tid % 94, c4 = tid / 94;
        int v0 = c4 << 4, v1 = min(v0 + 16, 79);
        float ss = 0.f;
#pragma unroll
        for (int t = 0; t < 16; ++t) ss += sb[(v0 + t)*SB_STR + u];
        vb[v0*VB_STR + u] = ss;
        for (int v = v0 + 1; v < v1; ++v) {
            ss += sb[(v+15)*SB_STR + u] - sb[(v-1)*SB_STR + u];
            vb[v*VB_STR + u] = ss;
        }
    }
    __syncthreads();

    if (tid < 474) {
        int v = tid % 79, ch = tid / 79;
        int u0 = (ch == 0) ? 0 : 14 + 13*(ch - 1);
        int u1 = (ch == 0) ? 14 : u0 + 13;
        const float* vr = vb + v*VB_STR;
        float bx = 0.f;
#pragma unroll
        for (int j = 0; j < 16; ++j) bx += vr[u0 + j];
        int gy = y0 - 7 + v;
        bool yok = (unsigned)gy < (unsigned)CROP;
        for (int u = u0; u < u1; ++u) {
            if (u > u0) bx += vr[u+15] - vr[u-1];
            float bp = 0.f;
            int gx = x0 - 7 + u;
            if (yok && (unsigned)gx < (unsigned)CROP)
                bp = sb[(v+7)*SB_STR + (u+7)] - bx * (1.0f/256.0f);
            sp[v*SP_STR + u] = bp;
        }
    }
    __syncthreads();

    for (int un = tid; un < 79*8; un += 512) {
        int v = un >> 3, ch = un & 7;
        int q0 = ch << 3;
        int gy = y0 - 7 + v;
        float av[24];
        if ((unsigned)gy < (unsigned)CROP) {
            const float* ar = apc + gy*CROP;
#pragma unroll
            for (int k = 0; k < 24; ++k) {
                int gx = x0 - 8 + q0 + k;
                av[k] = ((unsigned)gx < (unsigned)CROP) ? ar[gx] : 0.f;
            }
        } else {
#pragma unroll
            for (int k = 0; k < 24; ++k) av[k] = 0.f;
        }
        const float* bpr = sp + v*SP_STR;
        float s2 = 0.f, s3 = 0.f;
#pragma unroll
        for (int t = 0; t < 16; ++t) { float b_ = bpr[q0+t]; s2 += b_*b_; s3 += av[t+1]*b_; }
        float2* hr = h23 + v*H_STR;
        hr[q0] = make_float2(s2, s3);
#pragma unroll
        for (int st = 1; st < 8; ++st) {
            int q = q0 + st;
            float nb = bpr[q+15], ob = bpr[q-1];
            s2 += nb*nb - ob*ob;
            s3 += av[st+16]*nb - av[st]*ob;
            hr[q] = make_float2(s2, s3);
        }
    }
    __syncthreads();

    float acc = 0.f;
    const float* rsiic = g_sii + c*CIMG;
    {
        int q = tid & 63, seg = tid >> 6;
        int p0 = seg << 3;
        float s2 = 0.f, s3 = 0.f;
#pragma unroll
        for (int t = 0; t < 16; ++t) { float2 w = h23[(p0+t)*H_STR + q]; s2 += w.x; s3 += w.y; }
#pragma unroll
        for (int p = p0; p < p0 + 8; ++p) {
            if (p > p0) {
                float2 nw = h23[(p+15)*H_STR + q], ow = h23[(p-1)*H_STR + q];
                s2 += nw.x - ow.x;
                s3 += nw.y - ow.y;
            }
            int gy = y0 + p, gx = x0 + q;
            if (gy < CROP && gx < CROP) {
                float rj = rsqrtf(fmaxf(s2, 1e-20f));
                acc += s3 * rsiic[gy*CROP + gx] * rj;
            }
        }
    }

#pragma unroll
    for (int o = 16; o > 0; o >>= 1) acc += __shfl_down_sync(0xffffffffu, acc, o);
    if ((tid & 31) == 0) red[tid >> 5] = acc;
    __syncthreads();
    if (tid < 16) {
        float v = red[tid];
#pragma unroll
        for (int o = 8; o > 0; o >>= 1) v += __shfl_down_sync(0xffffu, v, o, 16);
        if (tid == 0) atomicAdd(&g_rho[z], (double)v);
    }
}

// ---------------- interior rho kernel: multi-shift groups ----------------
// One CTA = (group g, channel c, 64x64 interior tile). Group g = (mi, ne):
//   mi = g>>1, ne = g&1; shifts ni = 2k+ne, k in [0,L), L = ne?4:5; ci = k-2.
//   offx_k = 5-k; offx_min = 6-L; d_k = L-1-k.
// smem 18265 floats = 73.06 KB -> 3 CTAs/SM:
//   SBP [0,6715):      b' strip 79 x (79+L-1), stride 85
//   SA  [6715,13114):  a' 79x79, stride 81
//   H3  [13114,18249): hsum 79x64, stride 65
//   RED [18249,18265): 16-float reduction scratch
#define ISBP_OFF 0
#define ISBP_STR 85
#define ISA_OFF 6715
#define ISA_STR 81
#define IH3_OFF 13114
#define IH3_STR 65
#define IRED_OFF 18249
#define INT_SMEM_FLOATS 18265

__global__ void __launch_bounds__(512, 3)
k_rho_int()
{
    extern __shared__ float sm[];
    float* sbp = sm + ISBP_OFF;
    float* sa  = sm + ISA_OFF;
    float* h3  = sm + IH3_OFF;
    float* red = sm + IRED_OFF;

    const int z = blockIdx.z;
    const int g = z >> 3, c = z & 7;
    const int mi = g >> 1, ne = g & 1;
    const int L = ne ? 4 : 5;
    const int ri = (mi >> 1) - 2;
    const int pk = ((mi & 1) << 1) | ne;
    const int offy = 3 - ri;
    const int offx_min = 6 - L;
    const int y0 = ((int)blockIdx.y + 1) << 6, x0 = ((int)blockIdx.x + 1) << 6;
    const int tid = threadIdx.x;
    const float* bpc  = g_bp  + (pk*NCH + c)*IMG;
    const float* rsjc = g_sjj + (pk*NCH + c)*IMG;
    const float* apc  = g_ap + c*CIMG;
    const float* rsiic = g_sii + c*CIMG;
    const int WLD = 79 + L - 1;             // 83 or 82

    // phase 0: load b' strip and a' (interior: no guards needed)
    {
        const float* bprow0 = bpc + (y0 - 7 + offy)*512 + (x0 - 7 + offx_min);
        for (int k = tid; k < 79*WLD; k += 512) {
            int i = k / WLD, j = k - i*WLD;
            sbp[i*ISBP_STR + j] = bprow0[(i << 9) + j];
        }
        const float* aprow0 = apc + (y0 - 7)*CROP + (x0 - 7);
        for (int k = tid; k < 79*79; k += 512) {
            int i = k / 79, j = k - i*79;
            sa[i*ISA_STR + j] = aprow0[i*CROP + j];
        }
    }
    __syncthreads();

    // loop over shifts in the group
    for (int kk = 0; kk < L; ++kk) {
        const int d = L - 1 - kk;            // column offset into sbp
        const int offx = 5 - kk;             // rsjj column offset
        const int sidx = mi*9 + 2*kk + ne;   // shift index

        // phase 1: hsum16 of a'*b'(shifted) -> h3[79][64]
        for (int un = tid; un < 79*8; un += 512) {
            int v = un >> 3, ch = un & 7;
            int q0 = ch << 3;
            const float* ar  = sa  + v*ISA_STR;
            const float* bpr = sbp + v*ISBP_STR + d;
            float s3 = 0.f;
#pragma unroll
            for (int t = 0; t < 16; ++t) s3 += ar[q0+t] * bpr[q0+t];
            float* hr = h3 + v*IH3_STR;
            hr[q0] = s3;
#pragma unroll
            for (int st = 1; st < 8; ++st) {
                int q = q0 + st;
                s3 += ar[q+15]*bpr[q+15] - ar[q-1]*bpr[q-1];
                hr[q] = s3;
            }
        }
        __syncthreads();

        // phase 2: vsum16 -> rho epilogue (all outputs valid)
        float acc = 0.f;
        {
            int q = tid & 63, seg = tid >> 6;
            int p0 = seg << 3;
            float s3 = 0.f;
#pragma unroll
            for (int t = 0; t < 16; ++t) s3 += h3[(p0+t)*IH3_STR + q];
            const float* rsjrow = rsjc + offy*512 + offx + x0 + q;
#pragma unroll
            for (int p = p0; p < p0 + 8; ++p) {
                if (p > p0) s3 += h3[(p+15)*IH3_STR + q] - h3[(p-1)*IH3_STR + q];
                int gy = y0 + p, gx = x0 + q;
                acc += s3 * rsiic[gy*CROP + gx] * rsjrow[gy << 9];
            }
        }

        // per-shift reduction (red region disjoint from h3)
#pragma unroll
        for (int o = 16; o > 0; o >>= 1) acc += __shfl_down_sync(0xffffffffu, acc, o);
        if ((tid & 31) == 0) red[tid >> 5] = acc;
        __syncthreads();
        if (tid < 16) {
            float v = red[tid];
#pragma unroll
            for (int o = 8; o > 0; o >>= 1) v += __shfl_down_sync(0xffffu, v, o, 16);
            if (tid == 0) atomicAdd(&g_rho[sidx*NCH + c], (double)v);
        }
        // safe: next phase-1 writes h3 (disjoint from red); laggards are caught
        // by the phase-1-end barrier before red is rewritten
    }
}

__global__ void k_argmax(int* __restrict__ out) {
    int c = threadIdx.x;
    if (c >= NCH) return;
    double best = -1e300; int bi = 0;
    for (int s = 0; s < NSHIFT; ++s) {
        double v = g_rho[s*NCH + c];
        if (v > best) { best = v; bi = s; }
    }
    out[c]       = bi / 9 - 4;
    out[NCH + c] = bi % 9 - 4;
}

extern "C" void kernel_launch(void* const* d_in, const int* in_sizes, int n_in,
                              void* d_out, int out_size) {
    const float* ms  = (const float*)d_in[0];
    const float* pan = (const float*)d_in[1];
    const float* mtf = (const float*)d_in[2];
    int* out = (int*)d_out;
    (void)in_sizes; (void)n_in; (void)out_size;

    cudaFuncSetAttribute(k_rho_bnd, cudaFuncAttributeMaxDynamicSharedMemorySize,
                         SMEM_FLOATS * (int)sizeof(float));
    cudaFuncSetAttribute(k_rho_int, cudaFuncAttributeMaxDynamicSharedMemorySize,
                         INT_SMEM_FLOATS * (int)sizeof(float));

    k_zero<<<1, 656>>>();
    k_sepfac<<<NCH, 64>>>(mtf);
    k_gaussH<<<1024, 256>>>(pan);
    k_gaussV<<<1024, 256>>>();
    k_c13h<<<1024, 256>>>(0);
    k_c13v<<<1024, 256>>>(0);
    k_c13v<<<1024, 256>>>(1);

    k_ahsum <<<dim3(CROP, NCH), 64>>>(ms);
    k_aprime<<<dim3(4, 64, NCH), 128>>>(ms);
    k_sqh   <<<dim3(CROP, NCH), 64>>>();
    k_sii   <<<dim3(4, 64, NCH), 128>>>();

    k_bph<<<dim3(512, NCH, 4), 64>>>();
    k_bpv<<<dim3(4, 64, 4*NCH), 128>>>();
    k_sjh<<<dim3(512, NCH, 4), 64>>>();
    k_sjv<<<dim3(4, 64, 4*NCH), 128>>>();

    k_rho_bnd<<<dim3(28, 1, NSHIFT*NCH), 512, SMEM_FLOATS * (int)sizeof(float)>>>();
    // 18 groups x 8 channels in z; 6x6 interior tiles
    k_rho_int<<<dim3(6, 6, 18*NCH), 512, INT_SMEM_FLOATS * (int)sizeof(float)>>>();
    k_argmax<<<1, 32>>>(out);
}